// round 17
// baseline (speedup 1.0000x reference)
#include <cuda_runtime.h>
#include <math.h>

#define BN 4096
#define KN 3000
#define KPADC 3072        // padded columns
#define CN 8
#define NBLK 148
#define NTHR 1024
#define RPB 28            // ceil(4096/148)
#define CAP 1024          // max nz per row
#define COLCAP 768        // max nz per column (mean ~260, max ~330)
#define COLSP 21          // ceil(3000/148)
#define TOLF 1e-3f
#define THRESH -36.0f
#define FXSCALE 4398046511104.0f       // 2^42
#define FXINV   (1.0f/4398046511104.0f)

typedef unsigned long long ull;

// ---------------- static scratch ----------------
static __device__ unsigned short g_nzi[2][BN][CAP];   // CSR col idx
static __device__ float g_nzv[2][BN][CAP];            // CSR exp value
static __device__ float g_nzw[2][BN][CAP];            // CSR final P value
static __device__ int   g_cnt[2][BN];
static __device__ int      g_cbcnt[2][KPADC][NBLK];   // per (col, block) counts
static __device__ unsigned g_cbmeta[2][KPADC][NBLK];  // base(22b) | cnt<<22
static __device__ ull   g_csc[2][(size_t)KPADC * COLCAP]; // packed row | val<<32
static __device__ float g_r[2][BN];
static __device__ __align__(16) float g_u[2][BN];
static __device__ __align__(16) float g_v[2][KPADC];
static __device__ __align__(16) float g_v2[2][KPADC];
static __device__ volatile unsigned g_arrive[NBLK];   // barrier arrival flags
static __device__ volatile unsigned g_release;        // barrier release word
static __device__ volatile unsigned g_flagw[4];       // [slot][side]
static __device__ float g_rowent[2][BN];
static __device__ float g_rowmaxq[2][BN];
static __device__ float g_losspart[(size_t)CN * BN * 3];

struct Args {
    const float* lg[8];
    const int* ia;
    const int* ib;
};

__device__ __forceinline__ float warp_max(float v) {
#pragma unroll
    for (int o = 16; o; o >>= 1) v = fmaxf(v, __shfl_xor_sync(0xffffffffu, v, o));
    return v;
}
__device__ __forceinline__ float warp_sum(float v) {
#pragma unroll
    for (int o = 16; o; o >>= 1) v += __shfl_xor_sync(0xffffffffu, v, o);
    return v;
}

// ---------------- kernel 0: zero CSC counters ----------------
__global__ void __launch_bounds__(1024) zerocb_kernel() {
    size_t n = (size_t)2 * KPADC * NBLK;
    for (size_t j = (size_t)blockIdx.x * 1024 + threadIdx.x; j < n; j += (size_t)gridDim.x * 1024)
        ((int*)g_cbcnt)[j] = 0;
}

// ---------------- kernel 1: sparse build (single HBM pass) — R7 arithmetic ----------------
__global__ void __launch_bounds__(256) buildq_kernel(Args a) {
    __shared__ float s_x[KN];
    __shared__ float smx[8];
    __shared__ int s_wc[8], s_woff[8], s_base;

    const int s = blockIdx.y;
    const int row = blockIdx.x;
    const int idx = (s == 0) ? *a.ia : *a.ib;
    const float* __restrict__ xr = a.lg[idx] + (size_t)row * KN;
    const int tid = threadIdx.x, wid = tid >> 5, lane = tid & 31;

    // infra zeroing (once per launch — required for graph replay)
    if (blockIdx.x == 0 && s == 0) {
        if (tid < NBLK) g_arrive[tid] = 0u;
        if (tid < 4) g_flagw[tid] = 0u;
        if (tid == 0) g_release = 0u;
    }

    // single global pass: stage + row max
    float m = -3.402823466e38f;
    for (int k = tid; k < KN; k += 256) {
        float x = xr[k];
        s_x[k] = x;
        m = fmaxf(m, x);
    }
    m = warp_max(m);
    if (lane == 0) smx[wid] = m;
    __syncthreads();
    if (wid == 0) {
        float t = (lane < 8) ? smx[lane] : -3.402823466e38f;
        t = warp_max(t);
        if (lane == 0) smx[0] = t;
    }
    if (tid == 0) s_base = 0;
    __syncthreads();
    m = smx[0];

    // deterministic k-ordered compaction from smem (R7-exact) + per-(col,block) counts
    const int sbi = row / RPB;
    float rsum = 0.f;
    for (int k0 = 0; k0 < KN; k0 += 256) {
        const int col = k0 + tid;
        bool pred = false;
        float val = 0.f;
        if (col < KN) {
            float d = 20.0f * (s_x[col] - m);
            if (d > THRESH) { pred = true; val = __expf(d); }
        }
        unsigned mask = __ballot_sync(0xffffffffu, pred);
        int wcnt = __popc(mask);
        if (lane == 0) s_wc[wid] = wcnt;
        __syncthreads();
        if (tid == 0) {
            int b = s_base;
#pragma unroll
            for (int w = 0; w < 8; w++) { s_woff[w] = b; b += s_wc[w]; }
            s_base = b;
        }
        __syncthreads();
        if (pred) {
            int pos = s_woff[wid] + __popc(mask & ((1u << lane) - 1u));
            if (pos < CAP) {
                g_nzi[s][row][pos] = (unsigned short)col;
                g_nzv[s][row][pos] = val;
                rsum += val;
                atomicAdd(&g_cbcnt[s][col][sbi], 1);
            }
        }
        __syncthreads();
    }
    if (tid == 0) g_cnt[s][row] = min(s_base, CAP);

    rsum = warp_sum(rsum);
    if (lane == 0) smx[wid] = rsum;
    __syncthreads();
    if (wid == 0) {
        float t = (lane < 8) ? smx[lane] : 0.f;
        t = warp_sum(t);
        if (lane == 0) g_r[s][row] = t;
    }
}

// ---------------- kernel 1b: per-column prefix over blocks -> packed meta ----------------
__global__ void __launch_bounds__(1024) prefix_kernel() {
    int j = blockIdx.x * 1024 + threadIdx.x;
    if (j >= 2 * KPADC) return;
    int s = j / KPADC, k = j % KPADC;
    unsigned run = 0;
    for (int i = 0; i < NBLK; i++) {
        unsigned c = (unsigned)g_cbcnt[s][k][i];
        unsigned roff = min(run, (unsigned)COLCAP);
        unsigned ceff = min(c, (unsigned)COLCAP - roff);
        g_cbmeta[s][k][i] = ((unsigned)k * COLCAP + roff) | (ceff << 22);
        run += c;
    }
}

// ---------------- kernel 1c: CSC fill (smem cursors; within-segment order arbitrary) ----------------
__global__ void __launch_bounds__(256) fill_kernel() {
    __shared__ int scur[KPADC];
    const int s = blockIdx.y, bi = blockIdx.x, tid = threadIdx.x;
    const int row0 = bi * RPB;
    const int nrow = max(0, min(BN, row0 + RPB) - row0);
    for (int k = tid; k < KPADC; k += 256)
        scur[k] = (int)(g_cbmeta[s][k][bi] & 0x3FFFFFu);
    __syncthreads();
    for (int b = 0; b < nrow; b++) {
        const int row = row0 + b;
        const int cnt = g_cnt[s][row];
        for (int j = tid; j < cnt; j += 256) {
            int col = (int)g_nzi[s][row][j];
            float val = g_nzv[s][row][j];
            int pos = atomicAdd(&scur[col], 1);
            if (pos < (col + 1) * COLCAP)
                g_csc[s][(size_t)pos] = (ull)(unsigned)row | ((ull)__float_as_uint(val) << 32);
        }
    }
}

// ---------------- kernel 2: persistent double-Sinkhorn, exact CSC gather, 0 atomics ----------------
#define DSMEM_SZ 59392

__global__ void __launch_bounds__(NTHR, 1) sinkhorn_kernel() {
    extern __shared__ float dsm[];
    float* s_u = dsm;                  // [2][4096] staged u
    float* s_v = s_u + 2 * BN;         // [2][3072] staged v
    float* s_r = s_v + 2 * KPADC;      // [2][28]
    float* s_ucur = s_r + 2 * RPB;     // [2][28]
    float* s_uprev = s_ucur + 2 * RPB; // [2][28]
    int* s_cnt = (int*)(s_uprev + 2 * RPB);  // [2][28]

    const int tid = threadIdx.x, bi = blockIdx.x;
    const int wid = tid >> 5, lane = tid & 31;
    const float TGT = (float)(4096.0 / 3000.0);
    const int row0 = bi * RPB;
    const int nrow = max(0, min(BN, row0 + RPB) - row0);
    const int k0 = bi * COLSP;
    unsigned gen = 0;

// monitor-block grid barrier (R13-exact mechanics)
#define GRIDBAR() do { \
        __syncthreads(); \
        gen++; \
        if (tid == 0) { __threadfence(); g_arrive[bi] = gen; } \
        if (bi == 0) { \
            if (tid < NBLK) { while (g_arrive[tid] < gen) { } } \
            __syncthreads(); \
            if (tid == 0) { __threadfence(); g_release = gen; __threadfence(); } \
            __syncthreads(); \
        } else { \
            if (tid == 0) { while (g_release < gen) { } __threadfence(); } \
            __syncthreads(); \
        } \
    } while (0)

// stage u (both sides) from L2
#define STAGE_U() do { \
        const float4* up = (const float4*)&g_u[0][0]; \
        for (int j = tid; j < 2 * BN / 4; j += NTHR) ((float4*)s_u)[j] = __ldcg(up + j); \
        __syncthreads(); \
    } while (0)

// exact column gather for one (side, column): reproduces R7's per-block fixed-point
// partials and the stride-8 fp32 reduce order bit-for-bit.
#define COLGATHER(sv, kv, CEXPR) do { \
        float facc = 0.f; \
        for (int rnd = 0; rnd < 5; rnd++) { \
            const int i = rnd * 32 + lane; \
            float segval = 0.f; \
            if (i < NBLK) { \
                unsigned meta = g_cbmeta[sv][kv][i]; \
                int scnt = (int)(meta >> 22); \
                if (scnt > 0) { \
                    const ull* p = &g_csc[sv][(size_t)(meta & 0x3FFFFFu)]; \
                    ull acc = 0ull; \
                    for (int t2 = 0; t2 < scnt; t2++) { \
                        ull e = p[t2]; \
                        float t = s_u[(sv) * BN + (int)(e & 0xFFFFFFFFull)] \
                                  * __uint_as_float((unsigned)(e >> 32)); \
                        acc += __float2ull_rn(t * FXSCALE); \
                    } \
                    segval = (float)acc * FXINV; \
                } \
            } \
            float a0 = __shfl_sync(0xffffffffu, segval, lane & 7); \
            float a1 = __shfl_sync(0xffffffffu, segval, (lane & 7) + 8); \
            float a2 = __shfl_sync(0xffffffffu, segval, (lane & 7) + 16); \
            float a3 = __shfl_sync(0xffffffffu, segval, (lane & 7) + 24); \
            facc = ((((facc + a0) + a1) + a2) + a3); \
        } \
        float c = 0.f; \
        _Pragma("unroll") \
        for (int w = 0; w < 8; w++) c += __shfl_sync(0xffffffffu, facc, w); \
        if (lane == 0) { CEXPR; } \
    } while (0)

    // ---- init: u1 = 1/(r0+TINY) (R7-exact), publish ----
    for (int s = 0; s < 2; s++)
        if (tid < nrow) {
            float r = g_r[s][row0 + tid];
            s_r[s * RPB + tid] = r;
            s_cnt[s * RPB + tid] = g_cnt[s][row0 + tid];
            float u1 = 1.0f / (r + 1e-12f);
            s_ucur[s * RPB + tid] = u1;
            s_uprev[s * RPB + tid] = u1;
            g_u[s][row0 + tid] = u1;
        }
    GRIDBAR();

    bool done0 = false, done1 = false;
    int it = 1;
    while (true) {
        const int slot = it & 1;
        // ===== COL(it): stage u_t; exact gather c_t; v_t; col flag =====
        STAGE_U();
        for (int job = wid; job < 2 * COLSP; job += 32) {
            const int s = job / COLSP;
            if (s == 0 ? done0 : done1) continue;
            const int k = k0 + job % COLSP;
            if (k >= KN) continue;
            COLGATHER(s, k, {
                float v = TGT / (c + 1e-12f);
                g_v[s][k] = v;
                if (fabsf(v * c - TGT) > TOLF) g_flagw[slot * 2 + s] = 1u;
            });
        }
        GRIDBAR();   // BAR A: v + col flag visible
        // ===== ROW(it): zero next slot; stage v_t; gather r_t; row flag; u_{t+1} =====
        if (bi == 0 && tid < 2) g_flagw[((it + 1) & 1) * 2 + tid] = 0u;
        {
            const float4* vp = (const float4*)&g_v[0][0];
            for (int j = tid; j < 2 * KPADC / 4; j += NTHR) ((float4*)s_v)[j] = __ldcg(vp + j);
        }
        __syncthreads();
        for (int job = wid; job < 2 * RPB; job += 32) {
            const int s = job / RPB, b = job % RPB;
            if ((s == 0 ? done0 : done1) || b >= nrow) continue;
            const int cnt = s_cnt[s * RPB + b];
            const unsigned short* __restrict__ ri = g_nzi[s][row0 + b];
            const float* __restrict__ rv = g_nzv[s][row0 + b];
            float acc = 0.f;
            for (int i = lane; i < cnt; i += 32)
                acc = fmaf(rv[i], s_v[s * KPADC + ri[i]], acc);
            acc = warp_sum(acc);
            if (lane == 0) {
                float uold = s_ucur[s * RPB + b];
                s_uprev[s * RPB + b] = uold;
                s_r[s * RPB + b] = acc;
                float unew = 1.0f / (acc + 1e-12f);
                s_ucur[s * RPB + b] = unew;
                g_u[s][row0 + b] = unew;
                if (fabsf(uold * acc - 1.0f) > TOLF) g_flagw[slot * 2 + s] = 1u;
            }
        }
        GRIDBAR();   // BAR B: r/u/flags visible
        // ===== decision on iter it (R7-exact semantics) =====
        if (!done0) done0 = (it >= 3) && ((it >= 100) || (g_flagw[slot * 2 + 0] == 0u));
        if (!done1) done1 = (it >= 3) && ((it >= 100) || (g_flagw[slot * 2 + 1] == 0u));
        if (done0 && done1) break;
        it++;
    }

    // ---------------- finalize (R7-exact values) ----------------
    // F1: u1 = u_t/clip(u_t*r_t); publish
    for (int s = 0; s < 2; s++)
        if (tid < nrow) {
            float u = s_uprev[s * RPB + tid], r = s_r[s * RPB + tid];
            float u1 = u / fmaxf(u * r, 1e-12f);
            s_ucur[s * RPB + tid] = u1;
            g_u[s][row0 + tid] = u1;
        }
    GRIDBAR();
    // F2: exact gather c2 with u1; v2 = v_t*TGT/clip(v_t*c2)
    STAGE_U();
    for (int job = wid; job < 2 * COLSP; job += 32) {
        const int s = job / COLSP;
        const int k = k0 + job % COLSP;
        if (k >= KN) continue;
        COLGATHER(s, k, {
            float v = __ldcg((const float*)&g_v[s][k]);
            g_v2[s][k] = v * TGT / fmaxf(v * c, 1e-12f);
        });
    }
    GRIDBAR();
    // F3: r2 = Q v2; u2; entropy + rowmax; store w
    {
        const float4* vp = (const float4*)&g_v2[0][0];
        for (int j = tid; j < 2 * KPADC / 4; j += NTHR) ((float4*)s_v)[j] = __ldcg(vp + j);
    }
    __syncthreads();
    for (int job = wid; job < 2 * RPB; job += 32) {
        const int s = job / RPB, b = job % RPB;
        if (b >= nrow) continue;
        const int cnt = s_cnt[s * RPB + b];
        const unsigned short* __restrict__ ri = g_nzi[s][row0 + b];
        const float* __restrict__ rv = g_nzv[s][row0 + b];
        float acc = 0.f;
        for (int i = lane; i < cnt; i += 32)
            acc = fmaf(rv[i], s_v[s * KPADC + ri[i]], acc);
        acc = warp_sum(acc);
        float u1 = s_ucur[s * RPB + b];
        float u2 = u1 / fmaxf(u1 * acc, 1e-12f);
        float se = 0.f, mq = 0.f;
        for (int i = lane; i < cnt; i += 32) {
            float w = u2 * rv[i] * s_v[s * KPADC + ri[i]];
            g_nzw[s][row0 + b][i] = w;
            se = fmaf(w, __logf(w + 1e-12f), se);
            mq = fmaxf(mq, w);
        }
        se = warp_sum(se);
        mq = warp_max(mq);
        if (lane == 0) {
            g_rowent[s][row0 + b] = se;
            g_rowmaxq[s][row0 + b] = mq;
        }
    }
}

// ---------------- kernel 3: loss, one row per block, 8-warp dots ----------------
__global__ void __launch_bounds__(256) loss_kernel(Args a) {
    __shared__ __align__(16) float s_x[KN];
    __shared__ float s_red[8];
    __shared__ float s_part[8];
    const int tid = threadIdx.x, wid = tid >> 5, lane = tid & 31;
    const int c = blockIdx.y, b = blockIdx.x;
    const float* __restrict__ xr = a.lg[c] + (size_t)b * KN;

    // stage row to smem + registers; block max
    const float4* __restrict__ x4 = (const float4*)xr;
    float4* s4 = (float4*)s_x;
    float4 ra = __ldg(x4 + tid);
    float4 rb = __ldg(x4 + tid + 256);
    const bool hasc = (tid + 512) < KN / 4;
    float4 rc = hasc ? __ldg(x4 + tid + 512) : make_float4(-1e38f, -1e38f, -1e38f, -1e38f);
    s4[tid] = ra;
    s4[tid + 256] = rb;
    if (hasc) s4[tid + 512] = rc;

    float m = fmaxf(fmaxf(ra.x, ra.y), fmaxf(ra.z, ra.w));
    m = fmaxf(m, fmaxf(fmaxf(rb.x, rb.y), fmaxf(rb.z, rb.w)));
    m = fmaxf(m, fmaxf(fmaxf(rc.x, rc.y), fmaxf(rc.z, rc.w)));
    m = warp_max(m);
    if (lane == 0) s_red[wid] = m;
    __syncthreads();
    if (wid == 0) {
        float t = (lane < 8) ? s_red[lane] : -3.402823466e38f;
        t = warp_max(t);
        if (lane == 0) s_red[0] = t;
    }
    __syncthreads();
    m = s_red[0];
    __syncthreads();

    // lse from registers
    float se = 0.f;
    {
        float d;
        d = 10.0f * (ra.x - m); if (d > -18.f) se += __expf(d);
        d = 10.0f * (ra.y - m); if (d > -18.f) se += __expf(d);
        d = 10.0f * (ra.z - m); if (d > -18.f) se += __expf(d);
        d = 10.0f * (ra.w - m); if (d > -18.f) se += __expf(d);
        d = 10.0f * (rb.x - m); if (d > -18.f) se += __expf(d);
        d = 10.0f * (rb.y - m); if (d > -18.f) se += __expf(d);
        d = 10.0f * (rb.z - m); if (d > -18.f) se += __expf(d);
        d = 10.0f * (rb.w - m); if (d > -18.f) se += __expf(d);
        if (hasc) {
            d = 10.0f * (rc.x - m); if (d > -18.f) se += __expf(d);
            d = 10.0f * (rc.y - m); if (d > -18.f) se += __expf(d);
            d = 10.0f * (rc.z - m); if (d > -18.f) se += __expf(d);
            d = 10.0f * (rc.w - m); if (d > -18.f) se += __expf(d);
        }
    }
    se = warp_sum(se);
    if (lane == 0) s_red[wid] = se;

    // sparse dots across all 8 warps (fixed-order combine -> deterministic)
    {
        const int s = wid >> 2, sub = wid & 3;
        const int cnt = g_cnt[s][b];
        const unsigned short* __restrict__ ri = g_nzi[s][b];
        const float* __restrict__ wv = g_nzw[s][b];
        float dd = 0.f;
        for (int i = sub * 32 + lane; i < cnt; i += 128)
            dd = fmaf(wv[i], s_x[(int)ri[i]], dd);
        dd = warp_sum(dd);
        if (lane == 0) s_part[wid] = dd;
    }
    __syncthreads();
    if (tid == 0) {
        float ts = 0.f;
        for (int w = 0; w < 8; w++) ts += s_red[w];
        float ta = ((s_part[0] + s_part[1]) + s_part[2]) + s_part[3];
        float tb = ((s_part[4] + s_part[5]) + s_part[6]) + s_part[7];
        float* p = &g_losspart[((size_t)c * BN + b) * 3];
        p[0] = 10.0f * m + logf(ts);
        p[1] = ta;
        p[2] = tb;
    }
}

// ---------------- kernel 4: final scalar reduction ----------------
__device__ double bredD(double v, double* sd) {
    const int tid = threadIdx.x, wid = tid >> 5, lane = tid & 31;
#pragma unroll
    for (int o = 16; o; o >>= 1) v += __shfl_xor_sync(0xffffffffu, v, o);
    if (lane == 0) sd[wid] = v;
    __syncthreads();
    double t = 0.0;
    if (wid == 0) {
        t = sd[lane];
#pragma unroll
        for (int o = 16; o; o >>= 1) t += __shfl_xor_sync(0xffffffffu, t, o);
    }
    __syncthreads();
    return t;
}

__global__ void __launch_bounds__(1024) fin_kernel(Args a, float* out) {
    __shared__ double sd[32];
    const int tid = threadIdx.x;
    const int ia = *a.ia, ib = *a.ib;
    double se0 = 0, se1 = 0, sm0 = 0, sm1 = 0, sl = 0;
    for (int b = tid; b < BN; b += 1024) {
        se0 += (double)g_rowent[0][b];
        se1 += (double)g_rowent[1][b];
        sm0 += (double)g_rowmaxq[0][b];
        sm1 += (double)g_rowmaxq[1][b];
    }
    for (int i = tid; i < CN * BN; i += 1024) {
        int c = i / BN;
        const float* p = &g_losspart[(size_t)i * 3];
        double lse = p[0];
        if (c != ia) sl += lse - 10.0 * (double)p[1];
        if (c != ib) sl += lse - 10.0 * (double)p[2];
    }
    se0 = bredD(se0, sd);
    se1 = bredD(se1, sd);
    sm0 = bredD(sm0, sd);
    sm1 = bredD(sm1, sd);
    sl = bredD(sl, sd);
    if (tid == 0) {
        out[0] = (float)(sl / (14.0 * BN));
        out[1] = (float)(0.5 * ((-se0 / BN) + (-se1 / BN)));
        out[2] = (float)(0.5 * ((sm0 + sm1) / BN));
    }
}

// ---------------- entry ----------------
extern "C" void kernel_launch(void* const* d_in, const int* in_sizes, int n_in,
                              void* d_out, int out_size) {
    Args a;
    for (int i = 0; i < 8; i++) a.lg[i] = (const float*)d_in[i];
    a.ia = (const int*)d_in[8];
    a.ib = (const int*)d_in[9];

    cudaFuncSetAttribute(sinkhorn_kernel,
                         cudaFuncAttributeMaxDynamicSharedMemorySize, DSMEM_SZ);

    zerocb_kernel<<<NBLK, 1024>>>();
    buildq_kernel<<<dim3(BN, 2), 256>>>(a);
    prefix_kernel<<<6, 1024>>>();
    fill_kernel<<<dim3(NBLK, 2), 256>>>();
    sinkhorn_kernel<<<NBLK, NTHR, DSMEM_SZ>>>();
    loss_kernel<<<dim3(BN, CN), 256>>>(a);
    fin_kernel<<<1, 1024>>>(a, (float*)d_out);
}